// round 4
// baseline (speedup 1.0000x reference)
#include <cuda_runtime.h>
#include <cuda_bf16.h>
#include <stdint.h>

constexpr int CB = 16, CT = 2048, CN = 2048, CD = 128;
constexpr int BT = 128, BN = 64;
constexpr int NTILES = CN / BN;
constexpr float LOG2E = 1.4426950408889634f;
constexpr float LN2   = 0.6931471805599453f;

// Scratch (device globals — no allocation allowed)
__device__ float g_a1[CB * CT];
__device__ float g_a2[CB * CN];     // stores a2 * LOG2E
__device__ float g_m [CB * CT];
__device__ __align__(16) float g_h2[CB * CD];

// ---------------- smem layout (bytes) ----------------
constexpr int OFF_LRED = 0;                     // [2][128] f
constexpr int OFF_MRED = 1024;                  // [2][128] f
constexpr int OFF_A2S  = 2048;                  // [2][64] f
constexpr int OFF_AHI  = 4096;                  // 128*272
constexpr int OFF_ALO  = OFF_AHI + 34816;
constexpr int OFF_B    = OFF_ALO + 34816;       // 2 bufs x (hi 17408 | lo 17408)
constexpr int BUFSZ    = 34816;
constexpr int LOOFF    = 17408;
constexpr int OFF_PHI  = OFF_B + 2 * BUFSZ;     // 128*144
constexpr int OFF_PLO  = OFF_PHI + 18432;
constexpr int SMEM_SZ  = OFF_PLO + 18432;       // 180224
constexpr int OFF_HS   = OFF_AHI;               // epilogue float hs[128][132]

__device__ __forceinline__ uint32_t smem_u32(const void* p) {
    uint32_t a;
    asm("{ .reg .u64 t; cvta.to.shared.u64 t, %1; cvt.u32.u64 %0, t; }" : "=r"(a) : "l"(p));
    return a;
}
__device__ __forceinline__ void ldsm4(uint32_t* r, uint32_t a) {
    asm volatile("ldmatrix.sync.aligned.m8n8.x4.shared.b16 {%0,%1,%2,%3}, [%4];"
                 : "=r"(r[0]), "=r"(r[1]), "=r"(r[2]), "=r"(r[3]) : "r"(a));
}
__device__ __forceinline__ void ldsm4t(uint32_t* r, uint32_t a) {
    asm volatile("ldmatrix.sync.aligned.m8n8.x4.trans.shared.b16 {%0,%1,%2,%3}, [%4];"
                 : "=r"(r[0]), "=r"(r[1]), "=r"(r[2]), "=r"(r[3]) : "r"(a));
}
__device__ __forceinline__ void mma16816(float* c, const uint32_t* a, const uint32_t* b) {
    asm volatile(
        "mma.sync.aligned.m16n8k16.row.col.f32.bf16.bf16.f32 "
        "{%0,%1,%2,%3}, {%4,%5,%6,%7}, {%8,%9}, {%0,%1,%2,%3};"
        : "+f"(c[0]), "+f"(c[1]), "+f"(c[2]), "+f"(c[3])
        : "r"(a[0]), "r"(a[1]), "r"(a[2]), "r"(a[3]), "r"(b[0]), "r"(b[1]));
}
__device__ __forceinline__ float ex2(float x) {
    float r;
    asm("ex2.approx.ftz.f32 %0, %1;" : "=f"(r) : "f"(x));
    return r;
}

union BF4 { __nv_bfloat16 b[4]; uint2 u; };
union BF2 { __nv_bfloat16 b[2]; uint32_t u; };
__device__ __forceinline__ void split_store4(char* hi, char* lo, uint32_t o, float4 v) {
    BF4 H, L;
    H.b[0] = __float2bfloat16(v.x); L.b[0] = __float2bfloat16(v.x - __bfloat162float(H.b[0]));
    H.b[1] = __float2bfloat16(v.y); L.b[1] = __float2bfloat16(v.y - __bfloat162float(H.b[1]));
    H.b[2] = __float2bfloat16(v.z); L.b[2] = __float2bfloat16(v.z - __bfloat162float(H.b[2]));
    H.b[3] = __float2bfloat16(v.w); L.b[3] = __float2bfloat16(v.w - __bfloat162float(H.b[3]));
    *(uint2*)(hi + o) = H.u;
    *(uint2*)(lo + o) = L.u;
}

// ---------------------------------------------------------------------------
// K0: a1[b,t] = aud.w1 ; a2[b,n] = (sem.w2) * LOG2E
// ---------------------------------------------------------------------------
__global__ void prep_kernel(const float* __restrict__ aud,
                            const float* __restrict__ sem,
                            const float* __restrict__ W) {
    int gw = (blockIdx.x * blockDim.x + threadIdx.x) >> 5;
    int lane = threadIdx.x & 31;
    const int ROWS = CB * CT;
    bool isA = gw < ROWS;
    int row = isA ? gw : gw - ROWS;
    const float4* f = reinterpret_cast<const float4*>(isA ? aud : sem) + (size_t)row * (CD / 4);
    const float4* w = reinterpret_cast<const float4*>(W) + (isA ? 0 : CD / 4);
    float4 x = f[lane];
    float4 ww = w[lane];
    float s = x.x * ww.x + x.y * ww.y + x.z * ww.z + x.w * ww.w;
    #pragma unroll
    for (int o = 16; o > 0; o >>= 1) s += __shfl_xor_sync(0xffffffffu, s, o);
    if (lane == 0) {
        if (isA) g_a1[row] = s;
        else     g_a2[row] = s * LOG2E;
    }
}

// ---------------------------------------------------------------------------
// K1: split-bf16 mma.sync flash kernel, pipelined. CTA = (b, 128 t-rows).
// ---------------------------------------------------------------------------
__global__ void __launch_bounds__(256, 1)
flow_mma(const float* __restrict__ aud, const float* __restrict__ sem,
         const float* __restrict__ W, float* __restrict__ out) {
    extern __shared__ char smem[];
    const uint32_t sb = smem_u32(smem);
    const int tid = threadIdx.x, lane = tid & 31, w = tid >> 5;
    const int wm = w & 3, wn = w >> 2;
    const int q = lane >> 2, cp = lane & 3;
    const int b = blockIdx.y, t0 = blockIdx.x * BT;

    float* lred = (float*)(smem + OFF_LRED);
    float* mred = (float*)(smem + OFF_MRED);
    float* a2s  = (float*)(smem + OFF_A2S);

    const float* audb  = aud + (size_t)(b * CT + t0) * CD;
    const float* semb0 = sem + (size_t)(b * CN) * CD;

    const int prow = tid & 63, pc0 = (tid >> 6) * 32;

    // ---- A = (aud*w3) split-bf16 into smem; B tile 0 into buf0 ----
    {
        int row = tid >> 1, c0 = (tid & 1) * 64;
        #pragma unroll
        for (int cc = 0; cc < 16; cc++) {
            int col = c0 + cc * 4;
            float4 v  = *reinterpret_cast<const float4*>(audb + (size_t)row * CD + col);
            float4 wq = *reinterpret_cast<const float4*>(W + 2 * CD + col);
            v.x *= wq.x; v.y *= wq.y; v.z *= wq.z; v.w *= wq.w;
            split_store4(smem + OFF_AHI, smem + OFF_ALO, row * 272 + col * 2, v);
        }
        const float* sp = semb0 + (size_t)prow * CD;
        #pragma unroll
        for (int cc = 0; cc < 8; cc++) {
            float4 v = *reinterpret_cast<const float4*>(sp + pc0 + cc * 4);
            split_store4(smem + OFF_B, smem + OFF_B + LOOFF, prow * 272 + (pc0 + cc * 4) * 2, v);
        }
        if (tid < 64) a2s[tid] = g_a2[b * CN + tid];
    }
    __syncthreads();

    float oacc[2][8][4];
    #pragma unroll
    for (int mi = 0; mi < 2; mi++)
        #pragma unroll
        for (int d = 0; d < 8; d++)
            #pragma unroll
            for (int c = 0; c < 4; c++) oacc[mi][d][c] = 0.f;
    float lreg[2][2] = {{0.f, 0.f}, {0.f, 0.f}};
    float mreg[2][2] = {{-1e30f, -1e30f}, {-1e30f, -1e30f}};

    for (int it = 0; it < NTILES; it++) {
        const int cur = it & 1, nxt = cur ^ 1;
        const int itn = (it + 1 < NTILES) ? it + 1 : 0;

        // ---- prefetch next tile (LDG) + next a2 ----
        float4 pf[8];
        {
            const float* sp = semb0 + (size_t)(itn * BN + prow) * CD;
            #pragma unroll
            for (int cc = 0; cc < 8; cc++)
                pf[cc] = *reinterpret_cast<const float4*>(sp + pc0 + cc * 4);
            if (tid < 64) a2s[nxt * 64 + tid] = g_a2[b * CN + itn * BN + tid];
        }

        // ---- GEMM1: S[128,64] = A @ B^T (3-way split) ----
        float sacc[2][4][4];
        #pragma unroll
        for (int mi = 0; mi < 2; mi++)
            #pragma unroll
            for (int ni = 0; ni < 4; ni++)
                #pragma unroll
                for (int c = 0; c < 4; c++) sacc[mi][ni][c] = 0.f;

        const uint32_t bB = sb + OFF_B + cur * BUFSZ;
        #pragma unroll
        for (int kk = 0; kk < 8; kk++) {
            uint32_t Ah[2][4], Al[2][4];
            #pragma unroll
            for (int mi = 0; mi < 2; mi++) {
                uint32_t ra = sb + OFF_AHI + (wm * 32 + mi * 16 + (lane & 15)) * 272
                            + (kk * 16 + (lane >> 4) * 8) * 2;
                ldsm4(Ah[mi], ra);
                ldsm4(Al[mi], ra + (OFF_ALO - OFF_AHI));
            }
            #pragma unroll
            for (int nn = 0; nn < 2; nn++) {
                uint32_t Bh[4], Bl[4];
                uint32_t rb = bB + (wn * 32 + nn * 16 + (lane & 7) + ((lane >> 4) & 1) * 8) * 272
                            + (kk * 16 + ((lane >> 3) & 1) * 8) * 2;
                ldsm4(Bh, rb);
                ldsm4(Bl, rb + LOOFF);
                #pragma unroll
                for (int mi = 0; mi < 2; mi++)
                    #pragma unroll
                    for (int pp = 0; pp < 2; pp++) {
                        float* c = sacc[mi][nn * 2 + pp];
                        mma16816(c, Ah[mi], Bh + pp * 2);
                        mma16816(c, Ah[mi], Bl + pp * 2);
                        mma16816(c, Al[mi], Bh + pp * 2);
                    }
            }
        }

        // ---- softmax: P = exp2(S*log2e + a2l), l/m in registers ----
        #pragma unroll
        for (int mi = 0; mi < 2; mi++)
            #pragma unroll
            for (int ni = 0; ni < 4; ni++) {
                int col = wn * 32 + ni * 8 + 2 * cp;
                float a20 = a2s[cur * 64 + col], a21 = a2s[cur * 64 + col + 1];
                #pragma unroll
                for (int half = 0; half < 2; half++) {
                    float g0 = fmaf(sacc[mi][ni][half * 2],     LOG2E, a20);
                    float g1 = fmaf(sacc[mi][ni][half * 2 + 1], LOG2E, a21);
                    float p0 = ex2(g0), p1 = ex2(g1);
                    mreg[mi][half] = fmaxf(mreg[mi][half], fmaxf(g0, g1));
                    lreg[mi][half] += p0 + p1;
                    int row = wm * 32 + mi * 16 + q + half * 8;
                    BF2 H, L;
                    H.b[0] = __float2bfloat16(p0); L.b[0] = __float2bfloat16(p0 - __bfloat162float(H.b[0]));
                    H.b[1] = __float2bfloat16(p1); L.b[1] = __float2bfloat16(p1 - __bfloat162float(H.b[1]));
                    *(uint32_t*)(smem + OFF_PHI + row * 144 + col * 2) = H.u;
                    *(uint32_t*)(smem + OFF_PLO + row * 144 + col * 2) = L.u;
                }
            }
        __syncthreads();   // P ready; prev-iter readers of buf[nxt] done

        // ---- store prefetched tile into buf[nxt] ----
        if (it + 1 < NTILES) {
            char* hi = smem + OFF_B + nxt * BUFSZ;
            #pragma unroll
            for (int cc = 0; cc < 8; cc++)
                split_store4(hi, hi + LOOFF, prow * 272 + (pc0 + cc * 4) * 2, pf[cc]);
        }

        // ---- GEMM2: O += P @ V  (V = same sem tile via trans ldmatrix) ----
        #pragma unroll
        for (int kk = 0; kk < 4; kk++) {
            uint32_t Ph[2][4], Pl[2][4];
            #pragma unroll
            for (int mi = 0; mi < 2; mi++) {
                uint32_t rp = sb + OFF_PHI + (wm * 32 + mi * 16 + (lane & 15)) * 144
                            + (kk * 16 + (lane >> 4) * 8) * 2;
                ldsm4(Ph[mi], rp);
                ldsm4(Pl[mi], rp + (OFF_PLO - OFF_PHI));
            }
            #pragma unroll
            for (int dd = 0; dd < 4; dd++) {
                uint32_t Vh[4], Vl[4];
                uint32_t rv = bB + (kk * 16 + (lane & 7) + ((lane >> 3) & 1) * 8) * 272
                            + (wn * 64 + dd * 16 + (lane >> 4) * 8) * 2;
                ldsm4t(Vh, rv);
                ldsm4t(Vl, rv + LOOFF);
                #pragma unroll
                for (int mi = 0; mi < 2; mi++)
                    #pragma unroll
                    for (int pp = 0; pp < 2; pp++) {
                        float* c = oacc[mi][dd * 2 + pp];
                        mma16816(c, Ph[mi], Vh + pp * 2);
                        mma16816(c, Ph[mi], Vl + pp * 2);
                        mma16816(c, Pl[mi], Vh + pp * 2);
                    }
            }
        }
        __syncthreads();   // GEMM2 reads of P and buf[cur] done
    }

    // ---- combine l/m across lanes + wn warps ----
    #pragma unroll
    for (int mi = 0; mi < 2; mi++)
        #pragma unroll
        for (int half = 0; half < 2; half++) {
            float ls = lreg[mi][half], lm = mreg[mi][half];
            ls += __shfl_xor_sync(0xffffffffu, ls, 1);
            ls += __shfl_xor_sync(0xffffffffu, ls, 2);
            lm = fmaxf(lm, __shfl_xor_sync(0xffffffffu, lm, 1));
            lm = fmaxf(lm, __shfl_xor_sync(0xffffffffu, lm, 2));
            if (cp == 0) {
                int row = wm * 32 + mi * 16 + q + half * 8;
                lred[wn * 128 + row] = ls;
                mred[wn * 128 + row] = lm;
            }
        }
    __syncthreads();
    if (tid < 128) {
        float lt = lred[tid] + lred[128 + tid];
        float mt = fmaxf(mred[tid], mred[128 + tid]);
        lred[tid] = 1.0f / lt;
        g_m[b * CT + t0 + tid] = mt * LN2 + g_a1[b * CT + t0 + tid];
    }
    __syncthreads();

    // ---- epilogue: h = O * (1/l), stage in smem, coalesced writes ----
    float* hs = (float*)(smem + OFF_HS);
    #pragma unroll
    for (int mi = 0; mi < 2; mi++)
        #pragma unroll
        for (int half = 0; half < 2; half++) {
            int row = wm * 32 + mi * 16 + q + half * 8;
            float inv = lred[row];
            #pragma unroll
            for (int di = 0; di < 8; di++) {
                int col = wn * 64 + di * 8 + 2 * cp;
                float2 hv = make_float2(oacc[mi][di][half * 2] * inv,
                                        oacc[mi][di][half * 2 + 1] * inv);
                *reinterpret_cast<float2*>(&hs[row * 132 + col]) = hv;
            }
        }
    __syncthreads();

    #pragma unroll
    for (int e = 0; e < 16; e++) {
        int r = w + 8 * e;
        float4 a = reinterpret_cast<const float4*>(audb + (size_t)r * CD)[lane];
        float4 h = *reinterpret_cast<const float4*>(&hs[r * 132 + lane * 4]);
        float* orow = out + (size_t)(b * CT + t0 + r) * (4 * CD);
        reinterpret_cast<float4*>(orow)[lane] = a;
        reinterpret_cast<float4*>(orow + 128)[lane] = h;
        float4 m4 = make_float4(a.x * h.x, a.y * h.y, a.z * h.z, a.w * h.w);
        reinterpret_cast<float4*>(orow + 256)[lane] = m4;
    }
}

// ---------------------------------------------------------------------------
// K2: per batch: bw = softmax_t(m), h_con_a2[b,:] = sum_t bw[t]*aud[b,t,:]
// ---------------------------------------------------------------------------
__global__ void bw_kernel(const float* __restrict__ aud) {
    int b = blockIdx.x;
    int tid = threadIdx.x;
    __shared__ float red[256];
    __shared__ float wsh[CT];
    const float* mb = g_m + b * CT;
    float lm = -1e30f;
    for (int t = tid; t < CT; t += 256) lm = fmaxf(lm, mb[t]);
    red[tid] = lm; __syncthreads();
    for (int s = 128; s > 0; s >>= 1) { if (tid < s) red[tid] = fmaxf(red[tid], red[tid + s]); __syncthreads(); }
    float M = red[0]; __syncthreads();
    float ls = 0.f;
    for (int t = tid; t < CT; t += 256) { float e = __expf(mb[t] - M); wsh[t] = e; ls += e; }
    red[tid] = ls; __syncthreads();
    for (int s = 128; s > 0; s >>= 1) { if (tid < s) red[tid] += red[tid + s]; __syncthreads(); }
    float Z = red[0]; __syncthreads();
    int d = tid & 127, half = tid >> 7;
    const float* ab = aud + (size_t)(b * CT) * CD;
    float acc = 0.f;
    for (int t = half * (CT / 2); t < (half + 1) * (CT / 2); t++)
        acc = fmaf(wsh[t], ab[(size_t)t * CD + d], acc);
    red[tid] = acc; __syncthreads();
    if (tid < 128) g_h2[b * CD + tid] = (red[tid] + red[tid + 128]) / Z;
}

// ---------------------------------------------------------------------------
// K3: out[:,:,384:512] = aud * h_con_a2[b]
// ---------------------------------------------------------------------------
__global__ void out4_kernel(const float* __restrict__ aud, float* __restrict__ out) {
    int q = blockIdx.x * blockDim.x + threadIdx.x;
    int dq  = q & 31;
    int row = q >> 5;
    int b   = row >> 11;
    float4 a = reinterpret_cast<const float4*>(aud)[q];
    float4 h = reinterpret_cast<const float4*>(g_h2)[b * (CD / 4) + dq];
    float4 r;
    r.x = a.x * h.x; r.y = a.y * h.y; r.z = a.z * h.z; r.w = a.w * h.w;
    reinterpret_cast<float4*>(out)[(size_t)row * 128 + 96 + dq] = r;
}

// ---------------------------------------------------------------------------
extern "C" void kernel_launch(void* const* d_in, const int* in_sizes, int n_in,
                              void* d_out, int out_size) {
    const float* aud = (const float*)d_in[0];
    const float* sem = (const float*)d_in[1];
    const float* W   = (const float*)d_in[2];
    float* out = (float*)d_out;

    cudaFuncSetAttribute(flow_mma, cudaFuncAttributeMaxDynamicSharedMemorySize, SMEM_SZ);

    prep_kernel<<<8192, 256>>>(aud, sem, W);
    dim3 grid(CT / BT, CB);
    flow_mma<<<grid, 256, SMEM_SZ>>>(aud, sem, W, out);
    bw_kernel<<<CB, 256>>>(aud);
    out4_kernel<<<(CB * CT * CD / 4) / 256, 256>>>(aud, out);
}

// round 5
// speedup vs baseline: 2.0462x; 2.0462x over previous
#include <cuda_runtime.h>
#include <cuda_bf16.h>
#include <stdint.h>

constexpr int CB = 16, CT = 2048, CN = 2048, CD = 128;
constexpr int BT = 128, BN = 64;
constexpr int NTILES = CN / BN;
constexpr float LOG2E = 1.4426950408889634f;
constexpr float LN2   = 0.6931471805599453f;

// Scratch (device globals — no allocation allowed)
__device__ float g_a1[CB * CT];
__device__ float g_a2[CB * CN];     // stores a2 * LOG2E
__device__ float g_m [CB * CT];
__device__ __align__(16) float g_h2[CB * CD];

// ---------------- smem layout (bytes) ----------------
constexpr int OFF_LRED = 0;                      // [2][128] f
constexpr int OFF_MRED = 1024;                   // [2][128] f
constexpr int OFF_A2S  = 2048;                   // [2][64] f
constexpr int OFF_A    = 4096;                   // bf16 [128][136] stride 272 -> 34816
constexpr int OFF_B    = OFF_A + 34816;          // 2 x bf16 [64][136] stride 272 -> 17408 each
constexpr int BBUF     = 17408;
constexpr int OFF_P    = OFF_B + 2 * BBUF;       // bf16 [128][72] stride 144 -> 18432
constexpr int OFF_STG  = OFF_P + 18432;          // 2 x fp32 [64][132] stride 528 -> 33792 each
constexpr int SBUF     = 33792;
constexpr int SMEM_SZ  = OFF_STG + 2 * SBUF;     // 159744
constexpr int OFF_HS   = OFF_A;                  // epilogue float hs[128][132] (67584 <= A+B)

__device__ __forceinline__ uint32_t smem_u32(const void* p) {
    uint32_t a;
    asm("{ .reg .u64 t; cvta.to.shared.u64 t, %1; cvt.u32.u64 %0, t; }" : "=r"(a) : "l"(p));
    return a;
}
__device__ __forceinline__ void ldsm4(uint32_t* r, uint32_t a) {
    asm volatile("ldmatrix.sync.aligned.m8n8.x4.shared.b16 {%0,%1,%2,%3}, [%4];"
                 : "=r"(r[0]), "=r"(r[1]), "=r"(r[2]), "=r"(r[3]) : "r"(a));
}
__device__ __forceinline__ void ldsm4t(uint32_t* r, uint32_t a) {
    asm volatile("ldmatrix.sync.aligned.m8n8.x4.trans.shared.b16 {%0,%1,%2,%3}, [%4];"
                 : "=r"(r[0]), "=r"(r[1]), "=r"(r[2]), "=r"(r[3]) : "r"(a));
}
__device__ __forceinline__ void mma16816(float* c, const uint32_t* a, const uint32_t* b) {
    asm volatile(
        "mma.sync.aligned.m16n8k16.row.col.f32.bf16.bf16.f32 "
        "{%0,%1,%2,%3}, {%4,%5,%6,%7}, {%8,%9}, {%0,%1,%2,%3};"
        : "+f"(c[0]), "+f"(c[1]), "+f"(c[2]), "+f"(c[3])
        : "r"(a[0]), "r"(a[1]), "r"(a[2]), "r"(a[3]), "r"(b[0]), "r"(b[1]));
}
__device__ __forceinline__ float ex2(float x) {
    float r;
    asm("ex2.approx.ftz.f32 %0, %1;" : "=f"(r) : "f"(x));
    return r;
}
__device__ __forceinline__ void cpasync16(uint32_t saddr, const void* gaddr) {
    asm volatile("cp.async.cg.shared.global [%0], [%1], 16;" :: "r"(saddr), "l"(gaddr) : "memory");
}
__device__ __forceinline__ void cpasync_commit() {
    asm volatile("cp.async.commit_group;" ::: "memory");
}
__device__ __forceinline__ void cpasync_waitall() {
    asm volatile("cp.async.wait_group 0;" ::: "memory");
}

union BF4 { __nv_bfloat16 b[4]; uint2 u; };
union BF2 { __nv_bfloat16 b[2]; uint32_t u; };
__device__ __forceinline__ uint2 to_bf4(float4 v) {
    BF4 H;
    H.b[0] = __float2bfloat16(v.x);
    H.b[1] = __float2bfloat16(v.y);
    H.b[2] = __float2bfloat16(v.z);
    H.b[3] = __float2bfloat16(v.w);
    return H.u;
}

// ---------------------------------------------------------------------------
// K0: a1[b,t] = aud.w1 ; a2[b,n] = (sem.w2) * LOG2E
// ---------------------------------------------------------------------------
__global__ void prep_kernel(const float* __restrict__ aud,
                            const float* __restrict__ sem,
                            const float* __restrict__ W) {
    int gw = (blockIdx.x * blockDim.x + threadIdx.x) >> 5;
    int lane = threadIdx.x & 31;
    const int ROWS = CB * CT;
    bool isA = gw < ROWS;
    int row = isA ? gw : gw - ROWS;
    const float4* f = reinterpret_cast<const float4*>(isA ? aud : sem) + (size_t)row * (CD / 4);
    const float4* w = reinterpret_cast<const float4*>(W) + (isA ? 0 : CD / 4);
    float4 x = f[lane];
    float4 ww = w[lane];
    float s = x.x * ww.x + x.y * ww.y + x.z * ww.z + x.w * ww.w;
    #pragma unroll
    for (int o = 16; o > 0; o >>= 1) s += __shfl_xor_sync(0xffffffffu, s, o);
    if (lane == 0) {
        if (isA) g_a1[row] = s;
        else     g_a2[row] = s * LOG2E;
    }
}

// ---------------------------------------------------------------------------
// K1: single-pass bf16 mma.sync flash kernel with cp.async pipeline.
// CTA = (b, 128 t-rows), 8 warps. No max subtraction (|S|<~6).
// ---------------------------------------------------------------------------
__global__ void __launch_bounds__(256, 1)
flow_mma(const float* __restrict__ aud, const float* __restrict__ sem,
         const float* __restrict__ W, float* __restrict__ out) {
    extern __shared__ char smem[];
    const uint32_t sb = smem_u32(smem);
    const int tid = threadIdx.x, lane = tid & 31, w = tid >> 5;
    const int wm = w & 3, wn = w >> 2;
    const int q = lane >> 2, cp = lane & 3;
    const int b = blockIdx.y, t0 = blockIdx.x * BT;

    float* lred = (float*)(smem + OFF_LRED);
    float* mred = (float*)(smem + OFF_MRED);
    float* a2s  = (float*)(smem + OFF_A2S);

    const float* audb  = aud + (size_t)(b * CT + t0) * CD;
    const float* semb0 = sem + (size_t)(b * CN) * CD;

    const int prow = tid & 63, pc0 = (tid >> 6) * 32;

    // ---- prefetch B tiles 0,1 into fp32 staging via cp.async ----
    #pragma unroll
    for (int cc = 0; cc < 8; cc++)
        cpasync16(sb + OFF_STG + (prow * 132 + pc0 + cc * 4) * 4,
                  semb0 + (size_t)prow * CD + pc0 + cc * 4);
    cpasync_commit();
    #pragma unroll
    for (int cc = 0; cc < 8; cc++)
        cpasync16(sb + OFF_STG + SBUF + (prow * 132 + pc0 + cc * 4) * 4,
                  semb0 + (size_t)(BN + prow) * CD + pc0 + cc * 4);
    cpasync_commit();

    // ---- A = (aud*w3) bf16 into smem (overlaps with cp.async) ----
    {
        int row = tid >> 1, c0 = (tid & 1) * 64;
        #pragma unroll
        for (int cc = 0; cc < 16; cc++) {
            int col = c0 + cc * 4;
            float4 v  = *reinterpret_cast<const float4*>(audb + (size_t)row * CD + col);
            float4 wq = *reinterpret_cast<const float4*>(W + 2 * CD + col);
            v.x *= wq.x; v.y *= wq.y; v.z *= wq.z; v.w *= wq.w;
            *(uint2*)(smem + OFF_A + row * 272 + col * 2) = to_bf4(v);
        }
        if (tid < 64) a2s[tid] = g_a2[b * CN + tid];
    }

    // ---- convert stage0 -> B[0] (own region only) ----
    cpasync_waitall();
    {
        const float* stg = (const float*)(smem + OFF_STG);
        #pragma unroll
        for (int cc = 0; cc < 8; cc++) {
            int col = pc0 + cc * 4;
            float4 v = *reinterpret_cast<const float4*>(stg + prow * 132 + col);
            *(uint2*)(smem + OFF_B + prow * 272 + col * 2) = to_bf4(v);
        }
    }
    __syncthreads();

    float oacc[2][8][4];
    #pragma unroll
    for (int mi = 0; mi < 2; mi++)
        #pragma unroll
        for (int d = 0; d < 8; d++)
            #pragma unroll
            for (int c = 0; c < 4; c++) oacc[mi][d][c] = 0.f;
    float lreg[2][2] = {{0.f, 0.f}, {0.f, 0.f}};
    float mreg[2][2] = {{-1e30f, -1e30f}, {-1e30f, -1e30f}};

    for (int it = 0; it < NTILES; it++) {
        const int cur = it & 1, nxt = cur ^ 1;
        const uint32_t bB = sb + OFF_B + cur * BBUF;

        // ---- GEMM1: S[128,64] = A @ B^T ----
        float sacc[2][4][4];
        #pragma unroll
        for (int mi = 0; mi < 2; mi++)
            #pragma unroll
            for (int ni = 0; ni < 4; ni++)
                #pragma unroll
                for (int c = 0; c < 4; c++) sacc[mi][ni][c] = 0.f;

        #pragma unroll
        for (int kk = 0; kk < 8; kk++) {
            uint32_t Ah[2][4];
            #pragma unroll
            for (int mi = 0; mi < 2; mi++)
                ldsm4(Ah[mi], sb + OFF_A + (wm * 32 + mi * 16 + (lane & 15)) * 272
                              + (kk * 16 + (lane >> 4) * 8) * 2);
            #pragma unroll
            for (int nn = 0; nn < 2; nn++) {
                uint32_t Bh[4];
                ldsm4(Bh, bB + (wn * 32 + nn * 16 + (lane & 7) + ((lane >> 4) & 1) * 8) * 272
                          + (kk * 16 + ((lane >> 3) & 1) * 8) * 2);
                #pragma unroll
                for (int mi = 0; mi < 2; mi++)
                    #pragma unroll
                    for (int pp = 0; pp < 2; pp++)
                        mma16816(sacc[mi][nn * 2 + pp], Ah[mi], Bh + pp * 2);
            }
        }

        // ---- softmax: P = exp2(S*log2e + a2l); l/m in registers ----
        #pragma unroll
        for (int mi = 0; mi < 2; mi++)
            #pragma unroll
            for (int ni = 0; ni < 4; ni++) {
                int col = wn * 32 + ni * 8 + 2 * cp;
                float a20 = a2s[cur * 64 + col], a21 = a2s[cur * 64 + col + 1];
                #pragma unroll
                for (int half = 0; half < 2; half++) {
                    float g0 = fmaf(sacc[mi][ni][half * 2],     LOG2E, a20);
                    float g1 = fmaf(sacc[mi][ni][half * 2 + 1], LOG2E, a21);
                    float p0 = ex2(g0), p1 = ex2(g1);
                    mreg[mi][half] = fmaxf(mreg[mi][half], fmaxf(g0, g1));
                    lreg[mi][half] += p0 + p1;
                    int row = wm * 32 + mi * 16 + q + half * 8;
                    BF2 H;
                    H.b[0] = __float2bfloat16(p0);
                    H.b[1] = __float2bfloat16(p1);
                    *(uint32_t*)(smem + OFF_P + row * 144 + col * 2) = H.u;
                }
            }

        cpasync_waitall();          // tile it+1 resident in stage[nxt]
        __syncthreads();            // P visible; prev readers of B[nxt] done

        // ---- convert stage[nxt] -> B[nxt]; fetch tile it+2 -> stage[cur] ----
        if (it + 1 < NTILES) {
            const float* stg = (const float*)(smem + OFF_STG + nxt * SBUF);
            #pragma unroll
            for (int cc = 0; cc < 8; cc++) {
                int col = pc0 + cc * 4;
                float4 v = *reinterpret_cast<const float4*>(stg + prow * 132 + col);
                *(uint2*)(smem + OFF_B + nxt * BBUF + prow * 272 + col * 2) = to_bf4(v);
            }
            if (tid < 64) a2s[nxt * 64 + tid] = g_a2[b * CN + (it + 1) * BN + tid];
        }
        if (it + 2 < NTILES) {
            const float* gsrc = semb0 + (size_t)((it + 2) * BN + prow) * CD;
            #pragma unroll
            for (int cc = 0; cc < 8; cc++)
                cpasync16(sb + OFF_STG + cur * SBUF + (prow * 132 + pc0 + cc * 4) * 4,
                          gsrc + pc0 + cc * 4);
            cpasync_commit();
        }

        // ---- GEMM2: O += P @ V (V = same sem tile via trans ldmatrix) ----
        #pragma unroll
        for (int kk = 0; kk < 4; kk++) {
            uint32_t Ph[2][4];
            #pragma unroll
            for (int mi = 0; mi < 2; mi++)
                ldsm4(Ph[mi], sb + OFF_P + (wm * 32 + mi * 16 + (lane & 15)) * 144
                              + (kk * 16 + (lane >> 4) * 8) * 2);
            #pragma unroll
            for (int dd = 0; dd < 4; dd++) {
                uint32_t Vh[4];
                ldsm4t(Vh, bB + (kk * 16 + (lane & 7) + ((lane >> 3) & 1) * 8) * 272
                           + (wn * 64 + dd * 16 + (lane >> 4) * 8) * 2);
                #pragma unroll
                for (int mi = 0; mi < 2; mi++)
                    #pragma unroll
                    for (int pp = 0; pp < 2; pp++)
                        mma16816(oacc[mi][dd * 2 + pp], Ph[mi], Vh + pp * 2);
            }
        }
        __syncthreads();   // GEMM2 reads of P and B[cur] done
    }

    // ---- combine l/m across lanes + wn warps ----
    #pragma unroll
    for (int mi = 0; mi < 2; mi++)
        #pragma unroll
        for (int half = 0; half < 2; half++) {
            float ls = lreg[mi][half], lm = mreg[mi][half];
            ls += __shfl_xor_sync(0xffffffffu, ls, 1);
            ls += __shfl_xor_sync(0xffffffffu, ls, 2);
            lm = fmaxf(lm, __shfl_xor_sync(0xffffffffu, lm, 1));
            lm = fmaxf(lm, __shfl_xor_sync(0xffffffffu, lm, 2));
            if (cp == 0) {
                int row = wm * 32 + mi * 16 + q + half * 8;
                lred[wn * 128 + row] = ls;
                mred[wn * 128 + row] = lm;
            }
        }
    __syncthreads();
    if (tid < 128) {
        float lt = lred[tid] + lred[128 + tid];
        float mt = fmaxf(mred[tid], mred[128 + tid]);
        lred[tid] = 1.0f / lt;
        g_m[b * CT + t0 + tid] = mt * LN2 + g_a1[b * CT + t0 + tid];
    }
    __syncthreads();

    // ---- epilogue: h = O * (1/l), stage in smem, coalesced writes ----
    float* hs = (float*)(smem + OFF_HS);
    #pragma unroll
    for (int mi = 0; mi < 2; mi++)
        #pragma unroll
        for (int half = 0; half < 2; half++) {
            int row = wm * 32 + mi * 16 + q + half * 8;
            float inv = lred[row];
            #pragma unroll
            for (int di = 0; di < 8; di++) {
                int col = wn * 64 + di * 8 + 2 * cp;
                float2 hv = make_float2(oacc[mi][di][half * 2] * inv,
                                        oacc[mi][di][half * 2 + 1] * inv);
                *reinterpret_cast<float2*>(&hs[row * 132 + col]) = hv;
            }
        }
    __syncthreads();

    #pragma unroll
    for (int e = 0; e < 16; e++) {
        int r = w + 8 * e;
        float4 a = reinterpret_cast<const float4*>(audb + (size_t)r * CD)[lane];
        float4 h = *reinterpret_cast<const float4*>(&hs[r * 132 + lane * 4]);
        float* orow = out + (size_t)(b * CT + t0 + r) * (4 * CD);
        reinterpret_cast<float4*>(orow)[lane] = a;
        reinterpret_cast<float4*>(orow + 128)[lane] = h;
        float4 m4 = make_float4(a.x * h.x, a.y * h.y, a.z * h.z, a.w * h.w);
        reinterpret_cast<float4*>(orow + 256)[lane] = m4;
    }
}

// ---------------------------------------------------------------------------
// K2: per batch: bw = softmax_t(m), h_con_a2[b,:] = sum_t bw[t]*aud[b,t,:]
// ---------------------------------------------------------------------------
__global__ void bw_kernel(const float* __restrict__ aud) {
    int b = blockIdx.x;
    int tid = threadIdx.x;
    __shared__ float red[256];
    __shared__ float wsh[CT];
    const float* mb = g_m + b * CT;
    float lm = -1e30f;
    for (int t = tid; t < CT; t += 256) lm = fmaxf(lm, mb[t]);
    red[tid] = lm; __syncthreads();
    for (int s = 128; s > 0; s >>= 1) { if (tid < s) red[tid] = fmaxf(red[tid], red[tid + s]); __syncthreads(); }
    float M = red[0]; __syncthreads();
    float ls = 0.f;
    for (int t = tid; t < CT; t += 256) { float e = __expf(mb[t] - M); wsh[t] = e; ls += e; }
    red[tid] = ls; __syncthreads();
    for (int s = 128; s > 0; s >>= 1) { if (tid < s) red[tid] += red[tid + s]; __syncthreads(); }
    float Z = red[0]; __syncthreads();
    int d = tid & 127, half = tid >> 7;
    const float* ab = aud + (size_t)(b * CT) * CD;
    float acc = 0.f;
    for (int t = half * (CT / 2); t < (half + 1) * (CT / 2); t++)
        acc = fmaf(wsh[t], ab[(size_t)t * CD + d], acc);
    red[tid] = acc; __syncthreads();
    if (tid < 128) g_h2[b * CD + tid] = (red[tid] + red[tid + 128]) / Z;
}

// ---------------------------------------------------------------------------
// K3: out[:,:,384:512] = aud * h_con_a2[b]
// ---------------------------------------------------------------------------
__global__ void out4_kernel(const float* __restrict__ aud, float* __restrict__ out) {
    int q = blockIdx.x * blockDim.x + threadIdx.x;
    int dq  = q & 31;
    int row = q >> 5;
    int b   = row >> 11;
    float4 a = reinterpret_cast<const float4*>(aud)[q];
    float4 h = reinterpret_cast<const float4*>(g_h2)[b * (CD / 4) + dq];
    float4 r;
    r.x = a.x * h.x; r.y = a.y * h.y; r.z = a.z * h.z; r.w = a.w * h.w;
    reinterpret_cast<float4*>(out)[(size_t)row * 128 + 96 + dq] = r;
}

// ---------------------------------------------------------------------------
extern "C" void kernel_launch(void* const* d_in, const int* in_sizes, int n_in,
                              void* d_out, int out_size) {
    const float* aud = (const float*)d_in[0];
    const float* sem = (const float*)d_in[1];
    const float* W   = (const float*)d_in[2];
    float* out = (float*)d_out;

    cudaFuncSetAttribute(flow_mma, cudaFuncAttributeMaxDynamicSharedMemorySize, SMEM_SZ);

    prep_kernel<<<8192, 256>>>(aud, sem, W);
    dim3 grid(CT / BT, CB);
    flow_mma<<<grid, 256, SMEM_SZ>>>(aud, sem, W, out);
    bw_kernel<<<CB, 256>>>(aud);
    out4_kernel<<<(CB * CT * CD / 4) / 256, 256>>>(aud, out);
}

// round 6
// speedup vs baseline: 2.1967x; 1.0736x over previous
#include <cuda_runtime.h>
#include <cuda_bf16.h>
#include <stdint.h>

constexpr int CB = 16, CT = 2048, CN = 2048, CD = 128;
constexpr int BT = 128, BN = 64;
constexpr int NTILES = CN / BN;
constexpr float LOG2E = 1.4426950408889634f;
constexpr float LN2   = 0.6931471805599453f;

// Scratch (device globals — no allocation allowed)
__device__ float g_a1[CB * CT];
__device__ float g_a2[CB * CN];     // stores a2 * LOG2E
__device__ float g_m [CB * CT];
__device__ __align__(16) float g_h2[CB * CD];

// ---------------- smem layout (bytes) ----------------
constexpr int OFF_LRED = 0;                      // [2][128] f
constexpr int OFF_MRED = 1024;                   // [2][128] f
constexpr int OFF_A2S  = 2048;                   // [2][64] f
constexpr int OFF_A    = 4096;                   // bf16 [128][136] stride 272 -> 34816
constexpr int OFF_B    = OFF_A + 34816;          // 2 x bf16 [64][136] stride 272 -> 17408 each
constexpr int BBUF     = 17408;
constexpr int OFF_P    = OFF_B + 2 * BBUF;       // bf16 [128][72] stride 144 -> 18432
constexpr int OFF_STG  = OFF_P + 18432;          // 2 x fp32 [64][132] stride 528 -> 33792 each
constexpr int SBUF     = 33792;
constexpr int SMEM_SZ  = OFF_STG + 2 * SBUF;     // 159744
constexpr int OFF_HS   = OFF_A;                  // epilogue float hs[128][132]

__device__ __forceinline__ uint32_t smem_u32(const void* p) {
    uint32_t a;
    asm("{ .reg .u64 t; cvta.to.shared.u64 t, %1; cvt.u32.u64 %0, t; }" : "=r"(a) : "l"(p));
    return a;
}
__device__ __forceinline__ void ldsm4(uint32_t* r, uint32_t a) {
    asm volatile("ldmatrix.sync.aligned.m8n8.x4.shared.b16 {%0,%1,%2,%3}, [%4];"
                 : "=r"(r[0]), "=r"(r[1]), "=r"(r[2]), "=r"(r[3]) : "r"(a));
}
__device__ __forceinline__ void ldsm4t(uint32_t* r, uint32_t a) {
    asm volatile("ldmatrix.sync.aligned.m8n8.x4.trans.shared.b16 {%0,%1,%2,%3}, [%4];"
                 : "=r"(r[0]), "=r"(r[1]), "=r"(r[2]), "=r"(r[3]) : "r"(a));
}
__device__ __forceinline__ void mma16816(float* c, const uint32_t* a, const uint32_t* b) {
    asm volatile(
        "mma.sync.aligned.m16n8k16.row.col.f32.bf16.bf16.f32 "
        "{%0,%1,%2,%3}, {%4,%5,%6,%7}, {%8,%9}, {%0,%1,%2,%3};"
        : "+f"(c[0]), "+f"(c[1]), "+f"(c[2]), "+f"(c[3])
        : "r"(a[0]), "r"(a[1]), "r"(a[2]), "r"(a[3]), "r"(b[0]), "r"(b[1]));
}
__device__ __forceinline__ float ex2(float x) {
    float r;
    asm("ex2.approx.ftz.f32 %0, %1;" : "=f"(r) : "f"(x));
    return r;
}
__device__ __forceinline__ void cpasync16(uint32_t saddr, const void* gaddr) {
    asm volatile("cp.async.cg.shared.global [%0], [%1], 16;" :: "r"(saddr), "l"(gaddr) : "memory");
}
__device__ __forceinline__ void cpasync_commit() {
    asm volatile("cp.async.commit_group;" ::: "memory");
}
__device__ __forceinline__ void cpasync_waitall() {
    asm volatile("cp.async.wait_group 0;" ::: "memory");
}
__device__ __forceinline__ void bar64(int id) {
    asm volatile("bar.sync %0, 64;" :: "r"(id) : "memory");
}

union BF4 { __nv_bfloat16 b[4]; uint2 u; };
union BF2 { __nv_bfloat16 b[2]; uint32_t u; };
__device__ __forceinline__ uint2 to_bf4(float4 v) {
    BF4 H;
    H.b[0] = __float2bfloat16(v.x);
    H.b[1] = __float2bfloat16(v.y);
    H.b[2] = __float2bfloat16(v.z);
    H.b[3] = __float2bfloat16(v.w);
    return H.u;
}

// ---------------------------------------------------------------------------
// K0: a1[b,t] = aud.w1 ; a2[b,n] = (sem.w2) * LOG2E
// ---------------------------------------------------------------------------
__global__ void prep_kernel(const float* __restrict__ aud,
                            const float* __restrict__ sem,
                            const float* __restrict__ W) {
    int gw = (blockIdx.x * blockDim.x + threadIdx.x) >> 5;
    int lane = threadIdx.x & 31;
    const int ROWS = CB * CT;
    bool isA = gw < ROWS;
    int row = isA ? gw : gw - ROWS;
    const float4* f = reinterpret_cast<const float4*>(isA ? aud : sem) + (size_t)row * (CD / 4);
    const float4* w = reinterpret_cast<const float4*>(W) + (isA ? 0 : CD / 4);
    float4 x = f[lane];
    float4 ww = w[lane];
    float s = x.x * ww.x + x.y * ww.y + x.z * ww.z + x.w * ww.w;
    #pragma unroll
    for (int o = 16; o > 0; o >>= 1) s += __shfl_xor_sync(0xffffffffu, s, o);
    if (lane == 0) {
        if (isA) g_a1[row] = s;
        else     g_a2[row] = s * LOG2E;
    }
}

// ---------------------------------------------------------------------------
// K1: single-pass bf16 mma.sync flash kernel.
//  - A fragments register-resident across all n-tiles
//  - mid-tile sync is a 64-thread named barrier (warp pair sharing P rows)
// ---------------------------------------------------------------------------
__global__ void __launch_bounds__(256, 1)
flow_mma(const float* __restrict__ aud, const float* __restrict__ sem,
         const float* __restrict__ W, float* __restrict__ out) {
    extern __shared__ char smem[];
    const uint32_t sb = smem_u32(smem);
    const int tid = threadIdx.x, lane = tid & 31, w = tid >> 5;
    const int wm = w & 3, wn = w >> 2;
    const int q = lane >> 2, cp = lane & 3;
    const int b = blockIdx.y, t0 = blockIdx.x * BT;

    float* lred = (float*)(smem + OFF_LRED);
    float* mred = (float*)(smem + OFF_MRED);
    float* a2s  = (float*)(smem + OFF_A2S);

    const float* audb  = aud + (size_t)(b * CT + t0) * CD;
    const float* semb0 = sem + (size_t)(b * CN) * CD;

    const int prow = tid & 63, pc0 = (tid >> 6) * 32;

    // ---- prefetch B tiles 0,1 into fp32 staging via cp.async ----
    #pragma unroll
    for (int cc = 0; cc < 8; cc++)
        cpasync16(sb + OFF_STG + (prow * 132 + pc0 + cc * 4) * 4,
                  semb0 + (size_t)prow * CD + pc0 + cc * 4);
    cpasync_commit();
    #pragma unroll
    for (int cc = 0; cc < 8; cc++)
        cpasync16(sb + OFF_STG + SBUF + (prow * 132 + pc0 + cc * 4) * 4,
                  semb0 + (size_t)(BN + prow) * CD + pc0 + cc * 4);
    cpasync_commit();

    // ---- A = (aud*w3) bf16 into smem (overlaps with cp.async) ----
    {
        int row = tid >> 1, c0 = (tid & 1) * 64;
        #pragma unroll
        for (int cc = 0; cc < 16; cc++) {
            int col = c0 + cc * 4;
            float4 v  = *reinterpret_cast<const float4*>(audb + (size_t)row * CD + col);
            float4 wq = *reinterpret_cast<const float4*>(W + 2 * CD + col);
            v.x *= wq.x; v.y *= wq.y; v.z *= wq.z; v.w *= wq.w;
            *(uint2*)(smem + OFF_A + row * 272 + col * 2) = to_bf4(v);
        }
        if (tid < 64) a2s[tid] = g_a2[b * CN + tid];
    }

    // ---- convert stage0 -> B[0] (own region only) ----
    cpasync_waitall();
    {
        const float* stg = (const float*)(smem + OFF_STG);
        #pragma unroll
        for (int cc = 0; cc < 8; cc++) {
            int col = pc0 + cc * 4;
            float4 v = *reinterpret_cast<const float4*>(stg + prow * 132 + col);
            *(uint2*)(smem + OFF_B + prow * 272 + col * 2) = to_bf4(v);
        }
    }
    __syncthreads();

    // ---- A fragments: register-resident for the whole kernel ----
    uint32_t Afr[8][2][4];
    #pragma unroll
    for (int kk = 0; kk < 8; kk++)
        #pragma unroll
        for (int mi = 0; mi < 2; mi++)
            ldsm4(Afr[kk][mi], sb + OFF_A + (wm * 32 + mi * 16 + (lane & 15)) * 272
                               + (kk * 16 + (lane >> 4) * 8) * 2);

    float oacc[2][8][4];
    #pragma unroll
    for (int mi = 0; mi < 2; mi++)
        #pragma unroll
        for (int d = 0; d < 8; d++)
            #pragma unroll
            for (int c = 0; c < 4; c++) oacc[mi][d][c] = 0.f;
    float lreg[2][2] = {{0.f, 0.f}, {0.f, 0.f}};
    float mreg[2][2] = {{-1e30f, -1e30f}, {-1e30f, -1e30f}};

    for (int it = 0; it < NTILES; it++) {
        const int cur = it & 1, nxt = cur ^ 1;
        const uint32_t bB = sb + OFF_B + cur * BBUF;

        // ---- GEMM1: S[128,64] = A @ B^T ----
        float sacc[2][4][4];
        #pragma unroll
        for (int mi = 0; mi < 2; mi++)
            #pragma unroll
            for (int ni = 0; ni < 4; ni++)
                #pragma unroll
                for (int c = 0; c < 4; c++) sacc[mi][ni][c] = 0.f;

        #pragma unroll
        for (int kk = 0; kk < 8; kk++) {
            #pragma unroll
            for (int nn = 0; nn < 2; nn++) {
                uint32_t Bh[4];
                ldsm4(Bh, bB + (wn * 32 + nn * 16 + (lane & 7) + ((lane >> 4) & 1) * 8) * 272
                          + (kk * 16 + ((lane >> 3) & 1) * 8) * 2);
                #pragma unroll
                for (int mi = 0; mi < 2; mi++)
                    #pragma unroll
                    for (int pp = 0; pp < 2; pp++)
                        mma16816(sacc[mi][nn * 2 + pp], Afr[kk][mi], Bh + pp * 2);
            }
        }

        // ---- softmax: P = exp2(S*log2e + a2l); l/m in registers ----
        #pragma unroll
        for (int mi = 0; mi < 2; mi++)
            #pragma unroll
            for (int ni = 0; ni < 4; ni++) {
                int col = wn * 32 + ni * 8 + 2 * cp;
                float a20 = a2s[cur * 64 + col], a21 = a2s[cur * 64 + col + 1];
                #pragma unroll
                for (int half = 0; half < 2; half++) {
                    float g0 = fmaf(sacc[mi][ni][half * 2],     LOG2E, a20);
                    float g1 = fmaf(sacc[mi][ni][half * 2 + 1], LOG2E, a21);
                    float p0 = ex2(g0), p1 = ex2(g1);
                    mreg[mi][half] = fmaxf(mreg[mi][half], fmaxf(g0, g1));
                    lreg[mi][half] += p0 + p1;
                    int row = wm * 32 + mi * 16 + q + half * 8;
                    BF2 H;
                    H.b[0] = __float2bfloat16(p0);
                    H.b[1] = __float2bfloat16(p1);
                    *(uint32_t*)(smem + OFF_P + row * 144 + col * 2) = H.u;
                }
            }

        // P rows [wm*32, wm*32+32) touched only by warp pair {wm, wm+4}
        bar64(1 + wm);

        // ---- convert stage[nxt] -> B[nxt]; fetch tile it+2 -> stage[cur] ----
        if (it + 1 < NTILES) {
            cpasync_waitall();      // tile it+1 resident in stage[nxt]
            const float* stg = (const float*)(smem + OFF_STG + nxt * SBUF);
            #pragma unroll
            for (int cc = 0; cc < 8; cc++) {
                int col = pc0 + cc * 4;
                float4 v = *reinterpret_cast<const float4*>(stg + prow * 132 + col);
                *(uint2*)(smem + OFF_B + nxt * BBUF + prow * 272 + col * 2) = to_bf4(v);
            }
            if (tid < 64) a2s[nxt * 64 + tid] = g_a2[b * CN + (it + 1) * BN + tid];
        }
        if (it + 2 < NTILES) {
            const float* gsrc = semb0 + (size_t)((it + 2) * BN + prow) * CD;
            #pragma unroll
            for (int cc = 0; cc < 8; cc++)
                cpasync16(sb + OFF_STG + cur * SBUF + (prow * 132 + pc0 + cc * 4) * 4,
                          gsrc + pc0 + cc * 4);
            cpasync_commit();
        }

        // ---- GEMM2: O += P @ V (V = same sem tile via trans ldmatrix) ----
        #pragma unroll
        for (int kk = 0; kk < 4; kk++) {
            uint32_t Ph[2][4];
            #pragma unroll
            for (int mi = 0; mi < 2; mi++)
                ldsm4(Ph[mi], sb + OFF_P + (wm * 32 + mi * 16 + (lane & 15)) * 144
                              + (kk * 16 + (lane >> 4) * 8) * 2);
            #pragma unroll
            for (int dd = 0; dd < 4; dd++) {
                uint32_t Vh[4];
                ldsm4t(Vh, bB + (kk * 16 + (lane & 7) + ((lane >> 3) & 1) * 8) * 272
                           + (wn * 64 + dd * 16 + (lane >> 4) * 8) * 2);
                #pragma unroll
                for (int mi = 0; mi < 2; mi++)
                    #pragma unroll
                    for (int pp = 0; pp < 2; pp++)
                        mma16816(oacc[mi][dd * 2 + pp], Ph[mi], Vh + pp * 2);
            }
        }
        __syncthreads();   // B[cur]/P readers done; next iter may overwrite
    }

    // ---- combine l/m across lanes + wn warps ----
    #pragma unroll
    for (int mi = 0; mi < 2; mi++)
        #pragma unroll
        for (int half = 0; half < 2; half++) {
            float ls = lreg[mi][half], lm = mreg[mi][half];
            ls += __shfl_xor_sync(0xffffffffu, ls, 1);
            ls += __shfl_xor_sync(0xffffffffu, ls, 2);
            lm = fmaxf(lm, __shfl_xor_sync(0xffffffffu, lm, 1));
            lm = fmaxf(lm, __shfl_xor_sync(0xffffffffu, lm, 2));
            if (cp == 0) {
                int row = wm * 32 + mi * 16 + q + half * 8;
                lred[wn * 128 + row] = ls;
                mred[wn * 128 + row] = lm;
            }
        }
    __syncthreads();
    if (tid < 128) {
        float lt = lred[tid] + lred[128 + tid];
        float mt = fmaxf(mred[tid], mred[128 + tid]);
        lred[tid] = 1.0f / lt;
        g_m[b * CT + t0 + tid] = mt * LN2 + g_a1[b * CT + t0 + tid];
    }
    __syncthreads();

    // ---- epilogue: h = O * (1/l), stage in smem, coalesced writes ----
    float* hs = (float*)(smem + OFF_HS);
    #pragma unroll
    for (int mi = 0; mi < 2; mi++)
        #pragma unroll
        for (int half = 0; half < 2; half++) {
            int row = wm * 32 + mi * 16 + q + half * 8;
            float inv = lred[row];
            #pragma unroll
            for (int di = 0; di < 8; di++) {
                int col = wn * 64 + di * 8 + 2 * cp;
                float2 hv = make_float2(oacc[mi][di][half * 2] * inv,
                                        oacc[mi][di][half * 2 + 1] * inv);
                *reinterpret_cast<float2*>(&hs[row * 132 + col]) = hv;
            }
        }
    __syncthreads();

    #pragma unroll
    for (int e = 0; e < 16; e++) {
        int r = w + 8 * e;
        float4 a = reinterpret_cast<const float4*>(audb + (size_t)r * CD)[lane];
        float4 h = *reinterpret_cast<const float4*>(&hs[r * 132 + lane * 4]);
        float* orow = out + (size_t)(b * CT + t0 + r) * (4 * CD);
        reinterpret_cast<float4*>(orow)[lane] = a;
        reinterpret_cast<float4*>(orow + 128)[lane] = h;
        float4 m4 = make_float4(a.x * h.x, a.y * h.y, a.z * h.z, a.w * h.w);
        reinterpret_cast<float4*>(orow + 256)[lane] = m4;
    }
}

// ---------------------------------------------------------------------------
// K2: per batch: bw = softmax_t(m), h_con_a2[b,:] = sum_t bw[t]*aud[b,t,:]
// ---------------------------------------------------------------------------
__global__ void bw_kernel(const float* __restrict__ aud) {
    int b = blockIdx.x;
    int tid = threadIdx.x;
    __shared__ float red[256];
    __shared__ float wsh[CT];
    const float* mb = g_m + b * CT;
    float lm = -1e30f;
    for (int t = tid; t < CT; t += 256) lm = fmaxf(lm, mb[t]);
    red[tid] = lm; __syncthreads();
    for (int s = 128; s > 0; s >>= 1) { if (tid < s) red[tid] = fmaxf(red[tid], red[tid + s]); __syncthreads(); }
    float M = red[0]; __syncthreads();
    float ls = 0.f;
    for (int t = tid; t < CT; t += 256) { float e = __expf(mb[t] - M); wsh[t] = e; ls += e; }
    red[tid] = ls; __syncthreads();
    for (int s = 128; s > 0; s >>= 1) { if (tid < s) red[tid] += red[tid + s]; __syncthreads(); }
    float Z = red[0]; __syncthreads();
    int d = tid & 127, half = tid >> 7;
    const float* ab = aud + (size_t)(b * CT) * CD;
    float acc = 0.f;
    for (int t = half * (CT / 2); t < (half + 1) * (CT / 2); t++)
        acc = fmaf(wsh[t], ab[(size_t)t * CD + d], acc);
    red[tid] = acc; __syncthreads();
    if (tid < 128) g_h2[b * CD + tid] = (red[tid] + red[tid + 128]) / Z;
}

// ---------------------------------------------------------------------------
// K3: out[:,:,384:512] = aud * h_con_a2[b]
// ---------------------------------------------------------------------------
__global__ void out4_kernel(const float* __restrict__ aud, float* __restrict__ out) {
    int q = blockIdx.x * blockDim.x + threadIdx.x;
    int dq  = q & 31;
    int row = q >> 5;
    int b   = row >> 11;
    float4 a = reinterpret_cast<const float4*>(aud)[q];
    float4 h = reinterpret_cast<const float4*>(g_h2)[b * (CD / 4) + dq];
    float4 r;
    r.x = a.x * h.x; r.y = a.y * h.y; r.z = a.z * h.z; r.w = a.w * h.w;
    reinterpret_cast<float4*>(out)[(size_t)row * 128 + 96 + dq] = r;
}

// ---------------------------------------------------------------------------
extern "C" void kernel_launch(void* const* d_in, const int* in_sizes, int n_in,
                              void* d_out, int out_size) {
    const float* aud = (const float*)d_in[0];
    const float* sem = (const float*)d_in[1];
    const float* W   = (const float*)d_in[2];
    float* out = (float*)d_out;

    cudaFuncSetAttribute(flow_mma, cudaFuncAttributeMaxDynamicSharedMemorySize, SMEM_SZ);

    prep_kernel<<<8192, 256>>>(aud, sem, W);
    dim3 grid(CT / BT, CB);
    flow_mma<<<grid, 256, SMEM_SZ>>>(aud, sem, W, out);
    bw_kernel<<<CB, 256>>>(aud);
    out4_kernel<<<(CB * CT * CD / 4) / 256, 256>>>(aud, out);
}

// round 7
// speedup vs baseline: 2.2595x; 1.0286x over previous
#include <cuda_runtime.h>
#include <cuda_bf16.h>
#include <stdint.h>

constexpr int CB = 16, CT = 2048, CN = 2048, CD = 128;
constexpr int BT = 128, BN = 64;
constexpr int NTILES = CN / BN;
constexpr float LOG2E = 1.4426950408889634f;
constexpr float LN2   = 0.6931471805599453f;

// Scratch (device globals — no allocation allowed)
__device__ float g_a1[CB * CT];
__device__ float g_a2[CB * CN];     // stores a2 * LOG2E
__device__ float g_m [CB * CT];
__device__ __align__(16) float g_h2[CB * CD];

// ---------------- smem layout (bytes) ----------------
constexpr int OFF_A2S  = 0;                      // [2][64] f
constexpr int OFF_A    = 4096;                   // bf16 [128][136] stride 272 -> 34816
constexpr int OFF_B    = OFF_A + 34816;          // 2 x bf16 [64][136] stride 272
constexpr int BBUF     = 17408;
constexpr int OFF_STG  = OFF_B + 2 * BBUF;       // 2 x fp32 [64][132] stride 528
constexpr int SBUF     = 33792;
constexpr int SMEM_SZ  = OFF_STG + 2 * SBUF;     // 141312
constexpr int OFF_HS   = OFF_A;                  // epilogue float hs[128][132]

__device__ __forceinline__ uint32_t smem_u32(const void* p) {
    uint32_t a;
    asm("{ .reg .u64 t; cvta.to.shared.u64 t, %1; cvt.u32.u64 %0, t; }" : "=r"(a) : "l"(p));
    return a;
}
__device__ __forceinline__ void ldsm4(uint32_t* r, uint32_t a) {
    asm volatile("ldmatrix.sync.aligned.m8n8.x4.shared.b16 {%0,%1,%2,%3}, [%4];"
                 : "=r"(r[0]), "=r"(r[1]), "=r"(r[2]), "=r"(r[3]) : "r"(a));
}
__device__ __forceinline__ void ldsm4t(uint32_t* r, uint32_t a) {
    asm volatile("ldmatrix.sync.aligned.m8n8.x4.trans.shared.b16 {%0,%1,%2,%3}, [%4];"
                 : "=r"(r[0]), "=r"(r[1]), "=r"(r[2]), "=r"(r[3]) : "r"(a));
}
__device__ __forceinline__ void mma16816(float* c, const uint32_t* a, const uint32_t* b) {
    asm volatile(
        "mma.sync.aligned.m16n8k16.row.col.f32.bf16.bf16.f32 "
        "{%0,%1,%2,%3}, {%4,%5,%6,%7}, {%8,%9}, {%0,%1,%2,%3};"
        : "+f"(c[0]), "+f"(c[1]), "+f"(c[2]), "+f"(c[3])
        : "r"(a[0]), "r"(a[1]), "r"(a[2]), "r"(a[3]), "r"(b[0]), "r"(b[1]));
}
__device__ __forceinline__ float ex2(float x) {
    float r;
    asm("ex2.approx.ftz.f32 %0, %1;" : "=f"(r) : "f"(x));
    return r;
}
__device__ __forceinline__ uint32_t packbf(float lo, float hi) {
    uint32_t r;
    asm("cvt.rn.bf16x2.f32 %0, %1, %2;" : "=r"(r) : "f"(hi), "f"(lo));
    return r;
}
__device__ __forceinline__ void cpasync16(uint32_t saddr, const void* gaddr) {
    asm volatile("cp.async.cg.shared.global [%0], [%1], 16;" :: "r"(saddr), "l"(gaddr) : "memory");
}
__device__ __forceinline__ void cpasync_commit() {
    asm volatile("cp.async.commit_group;" ::: "memory");
}
__device__ __forceinline__ void cpasync_waitall() {
    asm volatile("cp.async.wait_group 0;" ::: "memory");
}

__device__ __forceinline__ uint2 to_bf4(float4 v) {
    return make_uint2(packbf(v.x, v.y), packbf(v.z, v.w));
}

// ---------------------------------------------------------------------------
// K0: a1[b,t] = aud.w1 ; a2[b,n] = (sem.w2) * LOG2E
// ---------------------------------------------------------------------------
__global__ void prep_kernel(const float* __restrict__ aud,
                            const float* __restrict__ sem,
                            const float* __restrict__ W) {
    int gw = (blockIdx.x * blockDim.x + threadIdx.x) >> 5;
    int lane = threadIdx.x & 31;
    const int ROWS = CB * CT;
    bool isA = gw < ROWS;
    int row = isA ? gw : gw - ROWS;
    const float4* f = reinterpret_cast<const float4*>(isA ? aud : sem) + (size_t)row * (CD / 4);
    const float4* w = reinterpret_cast<const float4*>(W) + (isA ? 0 : CD / 4);
    float4 x = f[lane];
    float4 ww = w[lane];
    float s = x.x * ww.x + x.y * ww.y + x.z * ww.z + x.w * ww.w;
    #pragma unroll
    for (int o = 16; o > 0; o >>= 1) s += __shfl_xor_sync(0xffffffffu, s, o);
    if (lane == 0) {
        if (isA) g_a1[row] = s;
        else     g_a2[row] = s * LOG2E;
    }
}

// ---------------------------------------------------------------------------
// K1: FA2-style register-P flash kernel. 8 warps; warp = 16 rows x full tile.
// P never touches smem: C-fragments of GEMM1 pack directly into A-fragments
// of GEMM2. Zero intra-tile barriers.
// ---------------------------------------------------------------------------
__global__ void __launch_bounds__(256, 1)
flow_mma(const float* __restrict__ aud, const float* __restrict__ sem,
         const float* __restrict__ W, float* __restrict__ out) {
    extern __shared__ char smem[];
    const uint32_t sb = smem_u32(smem);
    const int tid = threadIdx.x, lane = tid & 31, w = tid >> 5;
    const int q = lane >> 2, cp = lane & 3;
    const int b = blockIdx.y, t0 = blockIdx.x * BT;

    float* a2s = (float*)(smem + OFF_A2S);

    const float* audb  = aud + (size_t)(b * CT + t0) * CD;
    const float* semb0 = sem + (size_t)(b * CN) * CD;

    const int prow = tid & 63, pc0 = (tid >> 6) * 32;

    // ---- prefetch B tiles 0,1 into fp32 staging via cp.async ----
    #pragma unroll
    for (int cc = 0; cc < 8; cc++)
        cpasync16(sb + OFF_STG + (prow * 132 + pc0 + cc * 4) * 4,
                  semb0 + (size_t)prow * CD + pc0 + cc * 4);
    cpasync_commit();
    #pragma unroll
    for (int cc = 0; cc < 8; cc++)
        cpasync16(sb + OFF_STG + SBUF + (prow * 132 + pc0 + cc * 4) * 4,
                  semb0 + (size_t)(BN + prow) * CD + pc0 + cc * 4);
    cpasync_commit();

    // ---- A = (aud*w3) bf16 into smem (overlaps with cp.async) ----
    {
        int row = tid >> 1, c0 = (tid & 1) * 64;
        #pragma unroll
        for (int cc = 0; cc < 16; cc++) {
            int col = c0 + cc * 4;
            float4 v  = *reinterpret_cast<const float4*>(audb + (size_t)row * CD + col);
            float4 wq = *reinterpret_cast<const float4*>(W + 2 * CD + col);
            v.x *= wq.x; v.y *= wq.y; v.z *= wq.z; v.w *= wq.w;
            *(uint2*)(smem + OFF_A + row * 272 + col * 2) = to_bf4(v);
        }
        if (tid < 64) a2s[tid] = g_a2[b * CN + tid];
    }

    // ---- convert stage0 -> B[0] (own region only) ----
    cpasync_waitall();
    {
        const float* stg = (const float*)(smem + OFF_STG);
        #pragma unroll
        for (int cc = 0; cc < 8; cc++) {
            int col = pc0 + cc * 4;
            float4 v = *reinterpret_cast<const float4*>(stg + prow * 132 + col);
            *(uint2*)(smem + OFF_B + prow * 272 + col * 2) = to_bf4(v);
        }
    }
    __syncthreads();

    // ---- A fragments: rows [w*16, w*16+16), register-resident ----
    uint32_t Afr[8][4];
    #pragma unroll
    for (int kk = 0; kk < 8; kk++)
        ldsm4(Afr[kk], sb + OFF_A + (w * 16 + (lane & 15)) * 272
                       + (kk * 16 + (lane >> 4) * 8) * 2);

    float oacc[16][4];
    #pragma unroll
    for (int d = 0; d < 16; d++)
        #pragma unroll
        for (int c = 0; c < 4; c++) oacc[d][c] = 0.f;
    float lreg[2] = {0.f, 0.f};
    float mreg[2] = {-1e30f, -1e30f};

    for (int it = 0; it < NTILES; it++) {
        const int cur = it & 1, nxt = cur ^ 1;
        const uint32_t bB = sb + OFF_B + cur * BBUF;

        // ---- GEMM1: S[16,64] = A @ B^T (this warp's rows, all 64 cols) ----
        float sacc[8][4];
        #pragma unroll
        for (int ni = 0; ni < 8; ni++)
            #pragma unroll
            for (int c = 0; c < 4; c++) sacc[ni][c] = 0.f;

        #pragma unroll
        for (int kk = 0; kk < 8; kk++) {
            #pragma unroll
            for (int nn = 0; nn < 4; nn++) {
                uint32_t Bh[4];
                ldsm4(Bh, bB + (nn * 16 + (lane & 7) + ((lane >> 4) & 1) * 8) * 272
                          + (kk * 16 + ((lane >> 3) & 1) * 8) * 2);
                mma16816(sacc[nn * 2 + 0], Afr[kk], Bh + 0);
                mma16816(sacc[nn * 2 + 1], Afr[kk], Bh + 2);
            }
        }

        // ---- softmax: P = exp2(S*log2e + a2l), packed straight into
        //      GEMM2 A-fragments (C-layout == A-layout) ----
        uint32_t Pf[4][4];
        #pragma unroll
        for (int j = 0; j < 4; j++) {
            #pragma unroll
            for (int s = 0; s < 2; s++) {
                int ni = 2 * j + s;
                int col = ni * 8 + 2 * cp;
                float a20 = a2s[cur * 64 + col], a21 = a2s[cur * 64 + col + 1];
                float g0 = fmaf(sacc[ni][0], LOG2E, a20);
                float g1 = fmaf(sacc[ni][1], LOG2E, a21);
                float g2 = fmaf(sacc[ni][2], LOG2E, a20);
                float g3 = fmaf(sacc[ni][3], LOG2E, a21);
                float p0 = ex2(g0), p1 = ex2(g1), p2 = ex2(g2), p3 = ex2(g3);
                mreg[0] = fmaxf(mreg[0], fmaxf(g0, g1));
                mreg[1] = fmaxf(mreg[1], fmaxf(g2, g3));
                lreg[0] += p0 + p1;
                lreg[1] += p2 + p3;
                Pf[j][s * 2 + 0] = packbf(p0, p1);   // row q,   k-lo/hi half
                Pf[j][s * 2 + 1] = packbf(p2, p3);   // row q+8
            }
        }

        // ---- convert stage[nxt] -> B[nxt]; fetch tile it+2 -> stage[cur] ----
        if (it + 1 < NTILES) {
            cpasync_waitall();
            const float* stg = (const float*)(smem + OFF_STG + nxt * SBUF);
            #pragma unroll
            for (int cc = 0; cc < 8; cc++) {
                int col = pc0 + cc * 4;
                float4 v = *reinterpret_cast<const float4*>(stg + prow * 132 + col);
                *(uint2*)(smem + OFF_B + nxt * BBUF + prow * 272 + col * 2) = to_bf4(v);
            }
            if (tid < 64) a2s[nxt * 64 + tid] = g_a2[b * CN + (it + 1) * BN + tid];
        }
        if (it + 2 < NTILES) {
            const float* gsrc = semb0 + (size_t)((it + 2) * BN + prow) * CD;
            #pragma unroll
            for (int cc = 0; cc < 8; cc++)
                cpasync16(sb + OFF_STG + cur * SBUF + (prow * 132 + pc0 + cc * 4) * 4,
                          gsrc + pc0 + cc * 4);
            cpasync_commit();
        }

        // ---- GEMM2: O[16,128] += P @ V  (P in registers, V via ldsm4t) ----
        #pragma unroll
        for (int j = 0; j < 4; j++) {
            #pragma unroll
            for (int dd = 0; dd < 8; dd++) {
                uint32_t Vh[4];
                ldsm4t(Vh, bB + (j * 16 + (lane & 7) + ((lane >> 3) & 1) * 8) * 272
                           + (dd * 16 + (lane >> 4) * 8) * 2);
                mma16816(oacc[dd * 2 + 0], Pf[j], Vh + 0);
                mma16816(oacc[dd * 2 + 1], Pf[j], Vh + 2);
            }
        }
        __syncthreads();   // B[cur] readers done; next iter may overwrite
    }

    // ---- l/m: warp-local (each row owned by exactly one warp) ----
    float inv[2];
    #pragma unroll
    for (int half = 0; half < 2; half++) {
        float ls = lreg[half], lm = mreg[half];
        ls += __shfl_xor_sync(0xffffffffu, ls, 1);
        ls += __shfl_xor_sync(0xffffffffu, ls, 2);
        lm = fmaxf(lm, __shfl_xor_sync(0xffffffffu, lm, 1));
        lm = fmaxf(lm, __shfl_xor_sync(0xffffffffu, lm, 2));
        inv[half] = 1.0f / ls;
        if (cp == 0) {
            int row = w * 16 + q + half * 8;
            g_m[b * CT + t0 + row] = lm * LN2 + g_a1[b * CT + t0 + row];
        }
    }
    __syncthreads();   // A smem reads (Afr) long done; reuse as hs

    // ---- epilogue: h = O * (1/l), stage in smem, coalesced writes ----
    float* hs = (float*)(smem + OFF_HS);
    #pragma unroll
    for (int d2 = 0; d2 < 16; d2++) {
        int col = d2 * 8 + 2 * cp;
        int row0 = w * 16 + q;
        *reinterpret_cast<float2*>(&hs[row0 * 132 + col]) =
            make_float2(oacc[d2][0] * inv[0], oacc[d2][1] * inv[0]);
        *reinterpret_cast<float2*>(&hs[(row0 + 8) * 132 + col]) =
            make_float2(oacc[d2][2] * inv[1], oacc[d2][3] * inv[1]);
    }
    __syncthreads();

    #pragma unroll
    for (int e = 0; e < 16; e++) {
        int r = w + 8 * e;
        float4 a = reinterpret_cast<const float4*>(audb + (size_t)r * CD)[lane];
        float4 h = *reinterpret_cast<const float4*>(&hs[r * 132 + lane * 4]);
        float* orow = out + (size_t)(b * CT + t0 + r) * (4 * CD);
        reinterpret_cast<float4*>(orow)[lane] = a;
        reinterpret_cast<float4*>(orow + 128)[lane] = h;
        float4 m4 = make_float4(a.x * h.x, a.y * h.y, a.z * h.z, a.w * h.w);
        reinterpret_cast<float4*>(orow + 256)[lane] = m4;
    }
}

// ---------------------------------------------------------------------------
// K2: per batch: bw = softmax_t(m), h_con_a2[b,:] = sum_t bw[t]*aud[b,t,:]
// ---------------------------------------------------------------------------
__global__ void bw_kernel(const float* __restrict__ aud) {
    int b = blockIdx.x;
    int tid = threadIdx.x;
    __shared__ float red[256];
    __shared__ float wsh[CT];
    const float* mb = g_m + b * CT;
    float lm = -1e30f;
    for (int t = tid; t < CT; t += 256) lm = fmaxf(lm, mb[t]);
    red[tid] = lm; __syncthreads();
    for (int s = 128; s > 0; s >>= 1) { if (tid < s) red[tid] = fmaxf(red[tid], red[tid + s]); __syncthreads(); }
    float M = red[0]; __syncthreads();
    float ls = 0.f;
    for (int t = tid; t < CT; t += 256) { float e = __expf(mb[t] - M); wsh[t] = e; ls += e; }
    red[tid] = ls; __syncthreads();
    for (int s = 128; s > 0; s >>= 1) { if (tid < s) red[tid] += red[tid + s]; __syncthreads(); }
    float Z = red[0]; __syncthreads();
    int d = tid & 127, half = tid >> 7;
    const float* ab = aud + (size_t)(b * CT) * CD;
    float acc = 0.f;
    for (int t = half * (CT / 2); t < (half + 1) * (CT / 2); t++)
        acc = fmaf(wsh[t], ab[(size_t)t * CD + d], acc);
    red[tid] = acc; __syncthreads();
    if (tid < 128) g_h2[b * CD + tid] = (red[tid] + red[tid + 128]) / Z;
}

// ---------------------------------------------------------------------------
// K3: out[:,:,384:512] = aud * h_con_a2[b]
// ---------------------------------------------------------------------------
__global__ void out4_kernel(const float* __restrict__ aud, float* __restrict__ out) {
    int q = blockIdx.x * blockDim.x + threadIdx.x;
    int dq  = q & 31;
    int row = q >> 5;
    int b   = row >> 11;
    float4 a = reinterpret_cast<const float4*>(aud)[q];
    float4 h = reinterpret_cast<const float4*>(g_h2)[b * (CD / 4) + dq];
    float4 r;
    r.x = a.x * h.x; r.y = a.y * h.y; r.z = a.z * h.z; r.w = a.w * h.w;
    reinterpret_cast<float4*>(out)[(size_t)row * 128 + 96 + dq] = r;
}

// ---------------------------------------------------------------------------
extern "C" void kernel_launch(void* const* d_in, const int* in_sizes, int n_in,
                              void* d_out, int out_size) {
    const float* aud = (const float*)d_in[0];
    const float* sem = (const float*)d_in[1];
    const float* W   = (const float*)d_in[2];
    float* out = (float*)d_out;

    cudaFuncSetAttribute(flow_mma, cudaFuncAttributeMaxDynamicSharedMemorySize, SMEM_SZ);

    prep_kernel<<<8192, 256>>>(aud, sem, W);
    dim3 grid(CT / BT, CB);
    flow_mma<<<grid, 256, SMEM_SZ>>>(aud, sem, W, out);
    bw_kernel<<<CB, 256>>>(aud);
    out4_kernel<<<(CB * CT * CD / 4) / 256, 256>>>(aud, out);
}